// round 2
// baseline (speedup 1.0000x reference)
#include <cuda_runtime.h>
#include <cuda_bf16.h>
#include <math_constants.h>

// Problem constants
#define BB 2
#define LL 2048
#define DD 1024
#define HH 16
#define DKK 64
#define MM (BB * LL)          // 4096 rows for projections

// ---------------------------------------------------------------------------
// Scratch (device globals — no allocation allowed in kernel_launch)
// ---------------------------------------------------------------------------
__device__ float g_Q[BB * HH * LL * DKK];     // [b][h][l][d]
__device__ float g_K[BB * HH * LL * DKK];
__device__ float g_V[BB * HH * LL * DKK];
__device__ float g_attn[MM * DD];             // [b*L + l][h*64 + d]

// ---------------------------------------------------------------------------
// Shared GEMM microkernel body.
// C[M,N] = A[M,K] * W[N,K]^T + bias[N];  M=4096, N=1024, K=1024.
// 128x128 block tile, 16 k-slice, 8x8 microtile, 256 threads.
// ---------------------------------------------------------------------------
struct GemmCtx {
    const float* A;
    const float* W;
    const float* bias;
    int row0, col0, tx, ty, lr, lc;
};

__device__ __forceinline__ void gemm_tile(
    const GemmCtx& g, float (&acc)[8][8],
    float (*As)[128], float (*Bs)[128])
{
    const int K = DD;
    const float* Aptr = g.A + (size_t)(g.row0 + g.lr) * K + g.lc;
    const float* Wptr = g.W + (size_t)(g.col0 + g.lr) * K + g.lc;

#pragma unroll
    for (int u = 0; u < 8; u++)
#pragma unroll
        for (int v = 0; v < 8; v++) acc[u][v] = 0.0f;

    for (int kt = 0; kt < K; kt += 16) {
        float4 a0 = *(const float4*)(Aptr + kt);
        float4 a1 = *(const float4*)(Aptr + (size_t)64 * K + kt);
        float4 b0 = *(const float4*)(Wptr + kt);
        float4 b1 = *(const float4*)(Wptr + (size_t)64 * K + kt);

        __syncthreads();
        As[g.lc + 0][g.lr] = a0.x; As[g.lc + 1][g.lr] = a0.y;
        As[g.lc + 2][g.lr] = a0.z; As[g.lc + 3][g.lr] = a0.w;
        As[g.lc + 0][g.lr + 64] = a1.x; As[g.lc + 1][g.lr + 64] = a1.y;
        As[g.lc + 2][g.lr + 64] = a1.z; As[g.lc + 3][g.lr + 64] = a1.w;
        Bs[g.lc + 0][g.lr] = b0.x; Bs[g.lc + 1][g.lr] = b0.y;
        Bs[g.lc + 2][g.lr] = b0.z; Bs[g.lc + 3][g.lr] = b0.w;
        Bs[g.lc + 0][g.lr + 64] = b1.x; Bs[g.lc + 1][g.lr + 64] = b1.y;
        Bs[g.lc + 2][g.lr + 64] = b1.z; Bs[g.lc + 3][g.lr + 64] = b1.w;
        __syncthreads();

#pragma unroll
        for (int kk = 0; kk < 16; kk++) {
            // float4 shared reads: 4x LDS.128 instead of 16x LDS.32
            float4 aA = *(const float4*)&As[kk][g.ty * 8 + 0];
            float4 aB = *(const float4*)&As[kk][g.ty * 8 + 4];
            float4 bA = *(const float4*)&Bs[kk][g.tx * 8 + 0];
            float4 bB = *(const float4*)&Bs[kk][g.tx * 8 + 4];
            float a[8] = {aA.x, aA.y, aA.z, aA.w, aB.x, aB.y, aB.z, aB.w};
            float b[8] = {bA.x, bA.y, bA.z, bA.w, bB.x, bB.y, bB.z, bB.w};
#pragma unroll
            for (int u = 0; u < 8; u++)
#pragma unroll
                for (int v = 0; v < 8; v++) acc[u][v] += a[u] * b[v];
        }
    }
}

__device__ __forceinline__ GemmCtx make_ctx(
    const float* A, const float* W, const float* bias)
{
    GemmCtx g;
    g.A = A; g.W = W; g.bias = bias;
    g.row0 = blockIdx.y * 128;
    g.col0 = blockIdx.x * 128;
    int tid = threadIdx.x;
    g.tx = tid & 15;
    g.ty = tid >> 4;
    g.lr = tid >> 2;
    g.lc = (tid & 3) * 4;
    return g;
}

// ---------------------------------------------------------------------------
// Fused QKV projection: gridDim.z selects Q/K/V. Scatters into [b][h][l][d].
// ---------------------------------------------------------------------------
__global__ __launch_bounds__(256, 2) void qkv_gemm(
    const float* __restrict__ xq, const float* __restrict__ xk,
    const float* __restrict__ xv,
    const float* __restrict__ wq, const float* __restrict__ wk,
    const float* __restrict__ wv,
    const float* __restrict__ bq, const float* __restrict__ bk,
    const float* __restrict__ bv)
{
    __shared__ float As[16][128];
    __shared__ float Bs[16][128];

    int z = blockIdx.z;
    const float* A = (z == 0) ? xq : (z == 1) ? xk : xv;
    const float* W = (z == 0) ? wq : (z == 1) ? wk : wv;
    const float* bias = (z == 0) ? bq : (z == 1) ? bk : bv;
    float* dst = (z == 0) ? g_Q : (z == 1) ? g_K : g_V;

    GemmCtx g = make_ctx(A, W, bias);
    float acc[8][8];
    gemm_tile(g, acc, As, Bs);

#pragma unroll
    for (int u = 0; u < 8; u++) {
        int r = g.row0 + g.ty * 8 + u;
#pragma unroll
        for (int v = 0; v < 8; v++) {
            int c = g.col0 + g.tx * 8 + v;
            float val = acc[u][v] + bias[c];
            int bb = r >> 11;
            int l  = r & 2047;
            int h  = c >> 6;
            int d  = c & 63;
            dst[(((size_t)(bb * HH + h)) * LL + l) * DKK + d] = val;
        }
    }
}

// ---------------------------------------------------------------------------
// Output projection: reads g_attn, writes row-major d_out.
// ---------------------------------------------------------------------------
__global__ __launch_bounds__(256, 2) void out_gemm(
    const float* __restrict__ wo, const float* __restrict__ bo,
    float* __restrict__ Cout)
{
    __shared__ float As[16][128];
    __shared__ float Bs[16][128];

    GemmCtx g = make_ctx(g_attn, wo, bo);
    float acc[8][8];
    gemm_tile(g, acc, As, Bs);

#pragma unroll
    for (int u = 0; u < 8; u++) {
        int r = g.row0 + g.ty * 8 + u;
#pragma unroll
        for (int v = 0; v < 8; v++) {
            int c = g.col0 + g.tx * 8 + v;
            Cout[(size_t)r * DD + c] = acc[u][v] + bo[c];
        }
    }
}

// ---------------------------------------------------------------------------
// Flash attention, fp32, causal. 1 thread = 1 query row.
// Block: 128 threads (128 query rows). K/V tiles: 64 keys x 64 dims in smem.
// All lanes read the same K/V row -> smem broadcast, FMA-issue-bound.
// ---------------------------------------------------------------------------
__global__ __launch_bounds__(128) void flash_attn()
{
    __shared__ float Ks[64][64];
    __shared__ float Vs[64][64];

    int bh  = blockIdx.y;                    // 0..31 (= b*16 + h)
    int q0  = blockIdx.x * 128;
    int tid = threadIdx.x;
    int row = q0 + tid;

    const float* Qrow = g_Q + ((size_t)bh * LL + row) * DKK;
    const float* Kbh  = g_K + (size_t)bh * LL * DKK;
    const float* Vbh  = g_V + (size_t)bh * LL * DKK;

    const float inv_scale = 0.125f;          // 1/sqrt(64)

    float q[64];
#pragma unroll
    for (int d = 0; d < 64; d++) q[d] = Qrow[d] * inv_scale;

    float o[64];
#pragma unroll
    for (int d = 0; d < 64; d++) o[d] = 0.0f;
    float m = -CUDART_INF_F;
    float l = 0.0f;

    int nkt = (q0 >> 6) + 2;                 // key tiles covering [0, q0+127]

    for (int kt = 0; kt < nkt; kt++) {
        __syncthreads();
        for (int i = tid; i < 64 * 16; i += 128) {
            int r  = i >> 4;
            int c4 = (i & 15) * 4;
            size_t goff = ((size_t)(kt * 64 + r)) * DKK + c4;
            *(float4*)&Ks[r][c4] = *(const float4*)(Kbh + goff);
            *(float4*)&Vs[r][c4] = *(const float4*)(Vbh + goff);
        }
        __syncthreads();

        int kbase = kt * 64;
        int jmax  = row - kbase + 1;         // causal
        if (jmax > 64) jmax = 64;

        for (int j = 0; j < jmax; j++) {
            float s = 0.0f;
#pragma unroll
            for (int d = 0; d < 64; d++) s += q[d] * Ks[j][d];

            if (s > m) {                     // rare after warmup
                float c = __expf(m - s);
                m = s;
                l *= c;
#pragma unroll
                for (int d = 0; d < 64; d++) o[d] *= c;
            }
            float p = __expf(s - m);
            l += p;
#pragma unroll
            for (int d = 0; d < 64; d++) o[d] += p * Vs[j][d];
        }
    }

    float inv_l = 1.0f / l;
    int bb = bh >> 4;
    int h  = bh & 15;
    float* orow = g_attn + ((size_t)(bb * LL + row)) * DD + h * DKK;
#pragma unroll
    for (int d = 0; d < 64; d++) orow[d] = o[d] * inv_l;
}

// ---------------------------------------------------------------------------
// Launcher
// ---------------------------------------------------------------------------
extern "C" void kernel_launch(void* const* d_in, const int* in_sizes, int n_in,
                              void* d_out, int out_size)
{
    const float* query = (const float*)d_in[0];
    const float* key_  = (const float*)d_in[1];
    const float* value = (const float*)d_in[2];
    // d_in[3] = mask (causal; implemented structurally, not read)
    const float* w_q = (const float*)d_in[4];
    const float* b_q = (const float*)d_in[5];
    const float* w_k = (const float*)d_in[6];
    const float* b_k = (const float*)d_in[7];
    const float* w_v = (const float*)d_in[8];
    const float* b_v = (const float*)d_in[9];
    const float* w_o = (const float*)d_in[10];
    const float* b_o = (const float*)d_in[11];
    float* out = (float*)d_out;

    dim3 gq(DD / 128, MM / 128, 3);          // (8, 32, 3) fused QKV
    qkv_gemm<<<gq, 256>>>(query, key_, value, w_q, w_k, w_v, b_q, b_k, b_v);

    dim3 ga(LL / 128, BB * HH);              // (16, 32)
    flash_attn<<<ga, 128>>>();

    dim3 gg(DD / 128, MM / 128);             // (8, 32)
    out_gemm<<<gg, 256>>>(w_o, b_o, out);
}